// round 1
// baseline (speedup 1.0000x reference)
#include <cuda_runtime.h>
#include <math.h>

#define LQ      5
#define H       100
#define NB      16
#define TOK     (NB * LQ)      // 80 tokens per block
#define THREADS 320            // 16 token-groups x 20 col-groups
#define LD      101            // padded row stride in smem (gcd(101,32)=1)
#define KC      25             // K-chunk of W staged in smem

// Shared memory budget (floats):
//   s_sub, s_memv, s_raw(->sub_mem), s_m4a, s_s4a : 5 * 80*101 = 40400
//   s_w   : 25*100 = 2500
//   s_att : 80*5   = 400
//   s_len : 16 ints
#define SMEM_FLOATS (5 * TOK * LD + KC * H + TOK * LQ)
#define SMEM_BYTES  (SMEM_FLOATS * 4 + NB * 4)

#define ZERO_ACC()                           \
    _Pragma("unroll")                        \
    for (int i = 0; i < 5; i++)              \
        _Pragma("unroll")                    \
        for (int j = 0; j < 5; j++) acc[i][j] = 0.0f;

#define LOAD_W_CHUNK(PTR)                                                 \
    {                                                                     \
        const float4* gw = (const float4*)(PTR);                          \
        for (int i = tid; i < KC * H / 4; i += THREADS)                   \
            ((float4*)s_w)[i] = gw[i];                                    \
    }

// Inner product over one K-chunk. XLOAD may use (i, kk, koff).
#define GEMM_INNER(XLOAD)                                                 \
    for (int kk = 0; kk < KC; kk++) {                                     \
        const float* wrow = s_w + kk * H + c0;                            \
        float w0 = wrow[0], w1 = wrow[1], w2 = wrow[2],                   \
              w3 = wrow[3], w4 = wrow[4];                                 \
        _Pragma("unroll")                                                 \
        for (int i = 0; i < 5; i++) {                                     \
            float x = (XLOAD);                                            \
            acc[i][0] += x * w0;                                          \
            acc[i][1] += x * w1;                                          \
            acc[i][2] += x * w2;                                          \
            acc[i][3] += x * w3;                                          \
            acc[i][4] += x * w4;                                          \
        }                                                                 \
    }

__global__ __launch_bounds__(THREADS, 1)
void reading_memory_kernel(const float* __restrict__ sub_emb,
                           const float* __restrict__ memory,
                           const int*   __restrict__ sub_len,
                           const float* __restrict__ sub_raw,
                           const float* __restrict__ W_mem,
                           const float* __restrict__ b_mem,
                           const float* __restrict__ W_sub,
                           const float* __restrict__ b_sub,
                           const float* __restrict__ W_gate,
                           const float* __restrict__ b_gate,
                           float* __restrict__ out, int Btot)
{
    extern __shared__ float smem[];
    float* s_sub  = smem;                  // [80][101] sub_emb
    float* s_memv = s_sub  + TOK * LD;     // [80][101] memory
    float* s_raw  = s_memv + TOK * LD;     // [80][101] sub_emb_raw, later sub_mem
    float* s_m4a  = s_raw  + TOK * LD;     // [80][101] mem_4att
    float* s_s4a  = s_m4a  + TOK * LD;     // [80][101] sub_4att
    float* s_w    = s_s4a  + TOK * LD;     // [25][100] W chunk
    float* s_att  = s_w    + KC * H;       // [80][5]   attention
    int*   s_len  = (int*)(s_att + TOK * LQ);

    const int tid = threadIdx.x;
    const int b0  = blockIdx.x * NB;
    const int nb  = (Btot - b0 < NB) ? (Btot - b0) : NB;
    const int ntok = nb * LQ;

    // ---------------- Stage input tiles ----------------
    {
        const size_t base = (size_t)b0 * LQ * H;
        const float4* g_s = (const float4*)(sub_emb + base);
        const float4* g_m = (const float4*)(memory  + base);
        const float4* g_r = (const float4*)(sub_raw + base);
        const int nv = ntok * H / 4;
        for (int i = tid; i < nv; i += THREADS) {
            int flat = i * 4;
            int row = flat / H, col = flat - row * H;
            float4 a = g_s[i], m = g_m[i], r = g_r[i];
            float* ps = s_sub  + row * LD + col;
            float* pm = s_memv + row * LD + col;
            float* pr = s_raw  + row * LD + col;
            ps[0] = a.x; ps[1] = a.y; ps[2] = a.z; ps[3] = a.w;
            pm[0] = m.x; pm[1] = m.y; pm[2] = m.z; pm[3] = m.w;
            pr[0] = r.x; pr[1] = r.y; pr[2] = r.z; pr[3] = r.w;
        }
        // zero-fill unused rows on a partial tail block
        for (int i = ntok * H / 4 + tid; i < TOK * H / 4; i += THREADS) {
            int flat = i * 4;
            int row = flat / H, col = flat - row * H;
            float* ps = s_sub  + row * LD + col;
            float* pm = s_memv + row * LD + col;
            float* pr = s_raw  + row * LD + col;
            ps[0]=ps[1]=ps[2]=ps[3]=0.f;
            pm[0]=pm[1]=pm[2]=pm[3]=0.f;
            pr[0]=pr[1]=pr[2]=pr[3]=0.f;
        }
        if (tid < NB) s_len[tid] = (tid < nb) ? sub_len[b0 + tid] : 0;
    }
    __syncthreads();

    const int tx = tid % 20;
    const int ty = tid / 20;       // one batch per ty group
    const int c0 = tx * 5;
    const int r0 = ty * 5;

    float acc[5][5];

    // ---------------- GEMM1: mem_4att = tanh(memory @ W_mem + b_mem) ----------------
    ZERO_ACC();
    for (int kc0 = 0; kc0 < H; kc0 += KC) {
        LOAD_W_CHUNK(W_mem + kc0 * H);
        __syncthreads();
        GEMM_INNER(s_memv[(r0 + i) * LD + kc0 + kk]);
        __syncthreads();
    }
    #pragma unroll
    for (int j = 0; j < 5; j++) {
        float b = b_mem[c0 + j];
        #pragma unroll
        for (int i = 0; i < 5; i++)
            s_m4a[(r0 + i) * LD + c0 + j] = tanhf(acc[i][j] + b);
    }

    // ---------------- GEMM2: sub_4att = tanh([sub_emb|raw] @ W_sub + b_sub) ----------------
    ZERO_ACC();
    for (int kc0 = 0; kc0 < 2 * H; kc0 += KC) {
        LOAD_W_CHUNK(W_sub + kc0 * H);
        __syncthreads();
        const float* xb = (kc0 < H) ? s_sub : s_raw;
        const int koff = (kc0 < H) ? kc0 : (kc0 - H);
        GEMM_INNER(xb[(r0 + i) * LD + koff + kk]);
        __syncthreads();
    }
    #pragma unroll
    for (int j = 0; j < 5; j++) {
        float b = b_sub[c0 + j];
        #pragma unroll
        for (int i = 0; i < 5; i++)
            s_s4a[(r0 + i) * LD + c0 + j] = tanhf(acc[i][j] + b);
    }
    __syncthreads();

    // ---------------- Attention logits: att[q][k] = <sub_4att[q], mem_4att[k]> ----------------
    for (int p = tid; p < TOK * LQ; p += THREADS) {
        int q  = p / LQ;
        int kk = p - q * LQ;
        int bt = q / LQ;
        const float* aq = s_s4a + q * LD;
        const float* ak = s_m4a + (bt * LQ + kk) * LD;
        float d = 0.f;
        #pragma unroll 4
        for (int h = 0; h < H; h++) d += aq[h] * ak[h];
        s_att[p] = d;
    }
    __syncthreads();

    // ---------------- Softmax over keys + query-row mask ----------------
    // inf_mask is a per-row constant shift (broadcast over keys) -> softmax unchanged;
    // invalid rows are simply zeroed afterwards.
    for (int q = tid; q < TOK; q += THREADS) {
        int bt = q / LQ;
        int ql = q - bt * LQ;
        float* row = s_att + q * LQ;
        if (ql >= s_len[bt]) {
            #pragma unroll
            for (int k = 0; k < LQ; k++) row[k] = 0.f;
        } else {
            float m = row[0];
            #pragma unroll
            for (int k = 1; k < LQ; k++) m = fmaxf(m, row[k]);
            float e[LQ], s = 0.f;
            #pragma unroll
            for (int k = 0; k < LQ; k++) { e[k] = expf(row[k] - m); s += e[k]; }
            float inv = 1.f / s;
            #pragma unroll
            for (int k = 0; k < LQ; k++) row[k] = e[k] * inv;
        }
    }
    __syncthreads();

    // ---------------- sub_mem = att @ memory  (into s_raw, raw no longer needed) ----------------
    {
        float mv[5][5];
        #pragma unroll
        for (int k = 0; k < 5; k++)
            #pragma unroll
            for (int j = 0; j < 5; j++)
                mv[k][j] = s_memv[(r0 + k) * LD + c0 + j];
        #pragma unroll
        for (int i = 0; i < 5; i++) {
            float a0 = s_att[(r0 + i) * LQ + 0];
            float a1 = s_att[(r0 + i) * LQ + 1];
            float a2 = s_att[(r0 + i) * LQ + 2];
            float a3 = s_att[(r0 + i) * LQ + 3];
            float a4 = s_att[(r0 + i) * LQ + 4];
            #pragma unroll
            for (int j = 0; j < 5; j++)
                acc[i][j] = a0*mv[0][j] + a1*mv[1][j] + a2*mv[2][j]
                          + a3*mv[3][j] + a4*mv[4][j];
        }
        #pragma unroll
        for (int i = 0; i < 5; i++)
            #pragma unroll
            for (int j = 0; j < 5; j++)
                s_raw[(r0 + i) * LD + c0 + j] = acc[i][j];
    }
    __syncthreads();

    // ---------------- GEMM3: g = sigmoid([sub | sub_mem | sub*sub_mem] @ W_gate + b_gate) ----------------
    ZERO_ACC();
    for (int kc0 = 0; kc0 < 3 * H; kc0 += KC) {
        LOAD_W_CHUNK(W_gate + kc0 * H);
        __syncthreads();
        const int seg  = kc0 / H;
        const int koff = kc0 - seg * H;
        if (seg == 0) {
            GEMM_INNER(s_sub[(r0 + i) * LD + koff + kk]);
        } else if (seg == 1) {
            GEMM_INNER(s_raw[(r0 + i) * LD + koff + kk]);
        } else {
            GEMM_INNER(s_sub[(r0 + i) * LD + koff + kk] *
                       s_raw[(r0 + i) * LD + koff + kk]);
        }
        __syncthreads();
    }

    // ---------------- Gated output ----------------
    if (ty < nb) {
        #pragma unroll
        for (int j = 0; j < 5; j++) {
            float b = b_gate[c0 + j];
            #pragma unroll
            for (int i = 0; i < 5; i++) {
                float g = 1.f / (1.f + expf(-(acc[i][j] + b)));
                float e = s_sub[(r0 + i) * LD + c0 + j];
                float m = s_raw[(r0 + i) * LD + c0 + j];
                out[(size_t)(b0 + ty) * LQ * H + i * H + c0 + j] =
                    (1.f - g) * e + g * m;
            }
        }
    }
}

extern "C" void kernel_launch(void* const* d_in, const int* in_sizes, int n_in,
                              void* d_out, int out_size)
{
    const float* sub_emb = (const float*)d_in[0];
    const float* memory  = (const float*)d_in[1];
    const int*   sub_len = (const int*)  d_in[2];
    const float* sub_raw = (const float*)d_in[3];
    const float* W_mem   = (const float*)d_in[4];
    const float* b_mem   = (const float*)d_in[5];
    const float* W_sub   = (const float*)d_in[6];
    const float* b_sub   = (const float*)d_in[7];
    const float* W_gate  = (const float*)d_in[8];
    const float* b_gate  = (const float*)d_in[9];
    float* out = (float*)d_out;

    const int Btot = in_sizes[0] / (LQ * H);
    const int grid = (Btot + NB - 1) / NB;

    cudaFuncSetAttribute(reading_memory_kernel,
                         cudaFuncAttributeMaxDynamicSharedMemorySize, SMEM_BYTES);
    reading_memory_kernel<<<grid, THREADS, SMEM_BYTES>>>(
        sub_emb, memory, sub_len, sub_raw,
        W_mem, b_mem, W_sub, b_sub, W_gate, b_gate, out, Btot);
}

// round 4
// speedup vs baseline: 1.4121x; 1.4121x over previous
#include <cuda_runtime.h>
#include <math.h>

#define LQ      5
#define H       100
#define NB      12
#define TOK     (NB * LQ)          // 60 tokens / CTA
#define THREADS 320
#define ACTIVE  300                // 25 col-groups x 12 token-groups
#define LD      104                // padded smem row stride (x4 aligned)
#define KC      20                 // K-chunk of W staged in smem

// smem floats: 4 tile buffers + w chunk + att
#define SMEM_FLOATS (4 * TOK * LD + KC * LD + TOK * LQ)
#define SMEM_BYTES  (SMEM_FLOATS * 4 + NB * 4)

typedef unsigned long long u64;

__device__ __forceinline__ u64 pack2(float x) {
    unsigned int u = __float_as_uint(x);
    u64 r;
    asm("mov.b64 %0, {%1, %1};" : "=l"(r) : "r"(u));
    return r;
}
__device__ __forceinline__ void ffma2(u64& acc, u64 a, u64 b) {
    asm("fma.rn.f32x2 %0, %1, %2, %0;" : "+l"(acc) : "l"(a), "l"(b));
}
__device__ __forceinline__ void unpack2(u64 v, float& lo, float& hi) {
    unsigned int a, b;
    asm("mov.b64 {%0, %1}, %2;" : "=r"(a), "=r"(b) : "l"(v));
    lo = __uint_as_float(a); hi = __uint_as_float(b);
}

#define ZERO_ACC()                                  \
    _Pragma("unroll")                               \
    for (int i = 0; i < 5; i++) { acc[i][0] = 0ull; acc[i][1] = 0ull; }

#define STAGE_W(PTR)                                                     \
    {                                                                    \
        const float4* gw = (const float4*)(PTR);                         \
        for (int t = tid; t < KC * H / 4; t += THREADS) {                \
            float4 v = gw[t];                                            \
            int flat = t * 4;                                            \
            int rw = flat / H, cl = flat - rw * H;                       \
            *(float4*)(s_w + rw * LD + cl) = v;                          \
        }                                                                \
    }

// One K-chunk of FFMA2 GEMM. XV_STMT sets float4 xv using (i, kk, k0).
#define GEMM_CHUNK(XV_STMT)                                              \
    _Pragma("unroll")                                                    \
    for (int kk = 0; kk < KC; kk += 4) {                                 \
        ulonglong2 w0 = *(const ulonglong2*)(s_w + (kk + 0) * LD + c0);  \
        ulonglong2 w1 = *(const ulonglong2*)(s_w + (kk + 1) * LD + c0);  \
        ulonglong2 w2 = *(const ulonglong2*)(s_w + (kk + 2) * LD + c0);  \
        ulonglong2 w3 = *(const ulonglong2*)(s_w + (kk + 3) * LD + c0);  \
        _Pragma("unroll")                                                \
        for (int i = 0; i < 5; i++) {                                    \
            float4 xv; XV_STMT;                                          \
            u64 p0 = pack2(xv.x), p1 = pack2(xv.y);                      \
            u64 p2 = pack2(xv.z), p3 = pack2(xv.w);                      \
            ffma2(acc[i][0], p0, w0.x); ffma2(acc[i][1], p0, w0.y);      \
            ffma2(acc[i][0], p1, w1.x); ffma2(acc[i][1], p1, w1.y);      \
            ffma2(acc[i][0], p2, w2.x); ffma2(acc[i][1], p2, w2.y);      \
            ffma2(acc[i][0], p3, w3.x); ffma2(acc[i][1], p3, w3.y);      \
        }                                                                \
    }

__global__ __launch_bounds__(THREADS, 2)
void reading_memory_kernel(const float* __restrict__ sub_emb,
                           const float* __restrict__ memory,
                           const int*   __restrict__ sub_len,
                           const float* __restrict__ sub_raw,
                           const float* __restrict__ W_mem,
                           const float* __restrict__ b_mem,
                           const float* __restrict__ W_sub,
                           const float* __restrict__ b_sub,
                           const float* __restrict__ W_gate,
                           const float* __restrict__ b_gate,
                           float* __restrict__ out, int Btot)
{
    extern __shared__ float smem[];
    float* s_mem = smem;                   // [60][104] memory
    float* s_sub = s_mem + TOK * LD;       // [60][104] sub_emb
    float* s_c   = s_sub + TOK * LD;       // [60][104] raw -> sub_4att
    float* s_d   = s_c   + TOK * LD;       // [60][104] mem_4att -> sub_mem
    float* s_w   = s_d   + TOK * LD;       // [20][104] W chunk
    float* s_att = s_w   + KC * LD;        // [60][5]
    int*   s_len = (int*)(s_att + TOK * LQ);

    const int tid = threadIdx.x;
    const int b0  = blockIdx.x * NB;
    const int nb  = (Btot - b0 < NB) ? (Btot - b0) : NB;
    const int ntok = nb * LQ;

    // ---------------- Stage input tiles ----------------
    {
        const size_t base = (size_t)b0 * LQ * H;
        const float4* g_m = (const float4*)(memory  + base);
        const float4* g_s = (const float4*)(sub_emb + base);
        const float4* g_r = (const float4*)(sub_raw + base);
        const int nv = ntok * H / 4;
        for (int t = tid; t < TOK * H / 4; t += THREADS) {
            int flat = t * 4;
            int row = flat / H, col = flat - row * H;
            float4 m, s, r;
            if (t < nv) { m = g_m[t]; s = g_s[t]; r = g_r[t]; }
            else        { m = s = r = make_float4(0.f, 0.f, 0.f, 0.f); }
            *(float4*)(s_mem + row * LD + col) = m;
            *(float4*)(s_sub + row * LD + col) = s;
            *(float4*)(s_c   + row * LD + col) = r;
        }
        if (tid < NB) s_len[tid] = (tid < nb) ? sub_len[b0 + tid] : 0;
    }
    __syncthreads();

    const int tx = tid % 25;
    const int ty = tid / 25;          // batch index within tile (0..11 active)
    const int c0 = tx * 4;
    const int r0 = ty * 5;
    const bool act = (tid < ACTIVE);

    u64 acc[5][2];

    // ---------------- GEMM1: mem_4att = tanh(memory @ W_mem + b) -> s_d ----------------
    ZERO_ACC();
    for (int c = 0; c < H / KC; c++) {
        const int k0 = c * KC;
        STAGE_W(W_mem + k0 * H);
        __syncthreads();
        if (act) { GEMM_CHUNK(xv = *(const float4*)(s_mem + (r0 + i) * LD + k0 + kk)); }
        __syncthreads();
    }
    if (act) {
        float4 bv = *(const float4*)(b_mem + c0);
        #pragma unroll
        for (int i = 0; i < 5; i++) {
            float a0, a1, a2, a3;
            unpack2(acc[i][0], a0, a1); unpack2(acc[i][1], a2, a3);
            float4 o = make_float4(tanhf(a0 + bv.x), tanhf(a1 + bv.y),
                                   tanhf(a2 + bv.z), tanhf(a3 + bv.w));
            *(float4*)(s_d + (r0 + i) * LD + c0) = o;
        }
    }

    // ---------------- GEMM2: sub_4att = tanh([sub|raw] @ W_sub + b) -> s_c ----------------
    ZERO_ACC();
    for (int c = 0; c < 2 * H / KC; c++) {
        const int k0 = c * KC;
        STAGE_W(W_sub + k0 * H);
        __syncthreads();
        const float* xb = (k0 < H) ? s_sub : s_c;
        const int koff = (k0 < H) ? k0 : (k0 - H);
        if (act) { GEMM_CHUNK(xv = *(const float4*)(xb + (r0 + i) * LD + koff + kk)); }
        __syncthreads();   // last one also guards the raw->s4a overwrite below
    }
    if (act) {
        float4 bv = *(const float4*)(b_sub + c0);
        #pragma unroll
        for (int i = 0; i < 5; i++) {
            float a0, a1, a2, a3;
            unpack2(acc[i][0], a0, a1); unpack2(acc[i][1], a2, a3);
            float4 o = make_float4(tanhf(a0 + bv.x), tanhf(a1 + bv.y),
                                   tanhf(a2 + bv.z), tanhf(a3 + bv.w));
            *(float4*)(s_c + (r0 + i) * LD + c0) = o;
        }
    }
    __syncthreads();

    // ---------------- Attention logits: one (q, key) per thread ----------------
    if (tid < TOK * LQ) {
        const int q  = tid / LQ;
        const int ke = tid - q * LQ;
        const int bt = q / LQ;
        const float4* aq = (const float4*)(s_c + q * LD);
        const float4* ak = (const float4*)(s_d + (bt * LQ + ke) * LD);
        float d = 0.f;
        #pragma unroll
        for (int t = 0; t < H / 4; t++) {
            float4 a = aq[t], b = ak[t];
            d += a.x * b.x + a.y * b.y + a.z * b.z + a.w * b.w;
        }
        s_att[tid] = d;
    }
    __syncthreads();

    // ---------------- Softmax over keys + query-row mask ----------------
    if (tid < TOK) {
        const int bt = tid / LQ;
        const int ql = tid - bt * LQ;
        float* row = s_att + tid * LQ;
        if (ql >= s_len[bt]) {
            #pragma unroll
            for (int k = 0; k < LQ; k++) row[k] = 0.f;
        } else {
            float m = row[0];
            #pragma unroll
            for (int k = 1; k < LQ; k++) m = fmaxf(m, row[k]);
            float e[LQ], s = 0.f;
            #pragma unroll
            for (int k = 0; k < LQ; k++) { e[k] = expf(row[k] - m); s += e[k]; }
            float inv = 1.f / s;
            #pragma unroll
            for (int k = 0; k < LQ; k++) row[k] = e[k] * inv;
        }
    }
    __syncthreads();

    // ---------------- sub_mem = att @ memory -> s_d (m4a dead) ----------------
    if (act) {
        float4 mv[5];
        #pragma unroll
        for (int k = 0; k < 5; k++)
            mv[k] = *(const float4*)(s_mem + (ty * LQ + k) * LD + c0);
        #pragma unroll
        for (int i = 0; i < 5; i++) {
            const float* a = s_att + (r0 + i) * LQ;
            float4 o;
            o.x = a[0]*mv[0].x + a[1]*mv[1].x + a[2]*mv[2].x + a[3]*mv[3].x + a[4]*mv[4].x;
            o.y = a[0]*mv[0].y + a[1]*mv[1].y + a[2]*mv[2].y + a[3]*mv[3].y + a[4]*mv[4].y;
            o.z = a[0]*mv[0].z + a[1]*mv[1].z + a[2]*mv[2].z + a[3]*mv[3].z + a[4]*mv[4].z;
            o.w = a[0]*mv[0].w + a[1]*mv[1].w + a[2]*mv[2].w + a[3]*mv[3].w + a[4]*mv[4].w;
            acc[i][0] = 0ull;  // reuse acc as scratch store below (keeps regs tight)
            *(float4*)(s_d + (r0 + i) * LD + c0) = o;
        }
    }
    __syncthreads();

    // ---------------- GEMM3: g = sigmoid([sub | sub_mem | sub*sub_mem] @ W_gate + b) ----------------
    ZERO_ACC();
    for (int c = 0; c < H / KC; c++) {               // seg 0: sub_emb
        const int k0 = c * KC;
        STAGE_W(W_gate + k0 * H);
        __syncthreads();
        if (act) { GEMM_CHUNK(xv = *(const float4*)(s_sub + (r0 + i) * LD + k0 + kk)); }
        __syncthreads();
    }
    for (int c = 0; c < H / KC; c++) {               // seg 1: sub_mem
        const int k0 = c * KC;
        STAGE_W(W_gate + (H + k0) * H);
        __syncthreads();
        if (act) { GEMM_CHUNK(xv = *(const float4*)(s_d + (r0 + i) * LD + k0 + kk)); }
        __syncthreads();
    }
    for (int c = 0; c < H / KC; c++) {               // seg 2: sub_emb * sub_mem
        const int k0 = c * KC;
        STAGE_W(W_gate + (2 * H + k0) * H);
        __syncthreads();
        if (act) {
            GEMM_CHUNK(
                float4 xa = *(const float4*)(s_sub + (r0 + i) * LD + k0 + kk);
                float4 xb = *(const float4*)(s_d   + (r0 + i) * LD + k0 + kk);
                xv = make_float4(xa.x * xb.x, xa.y * xb.y, xa.z * xb.z, xa.w * xb.w));
        }
        __syncthreads();
    }

    // ---------------- Gated output ----------------
    if (act && ty < nb) {
        float4 bv = *(const float4*)(b_gate + c0);
        #pragma unroll
        for (int i = 0; i < 5; i++) {
            float a0, a1, a2, a3;
            unpack2(acc[i][0], a0, a1); unpack2(acc[i][1], a2, a3);
            float4 e = *(const float4*)(s_sub + (r0 + i) * LD + c0);
            float4 m = *(const float4*)(s_d   + (r0 + i) * LD + c0);
            float g0 = 1.f / (1.f + expf(-(a0 + bv.x)));
            float g1 = 1.f / (1.f + expf(-(a1 + bv.y)));
            float g2 = 1.f / (1.f + expf(-(a2 + bv.z)));
            float g3 = 1.f / (1.f + expf(-(a3 + bv.w)));
            float4 o = make_float4((1.f - g0) * e.x + g0 * m.x,
                                   (1.f - g1) * e.y + g1 * m.y,
                                   (1.f - g2) * e.z + g2 * m.z,
                                   (1.f - g3) * e.w + g3 * m.w);
            *(float4*)(out + (size_t)(b0 + ty) * LQ * H + i * H + c0) = o;
        }
    }
}

extern "C" void kernel_launch(void* const* d_in, const int* in_sizes, int n_in,
                              void* d_out, int out_size)
{
    const float* sub_emb = (const float*)d_in[0];
    const float* memory  = (const float*)d_in[1];
    const int*   sub_len = (const int*)  d_in[2];
    const float* sub_raw = (const float*)d_in[3];
    const float* W_mem   = (const float*)d_in[4];
    const float* b_mem   = (const float*)d_in[5];
    const float* W_sub   = (const float*)d_in[6];
    const float* b_sub   = (const float*)d_in[7];
    const float* W_gate  = (const float*)d_in[8];
    const float* b_gate  = (const float*)d_in[9];
    float* out = (float*)d_out;

    const int Btot = in_sizes[0] / (LQ * H);
    const int grid = (Btot + NB - 1) / NB;

    cudaFuncSetAttribute(reading_memory_kernel,
                         cudaFuncAttributeMaxDynamicSharedMemorySize, SMEM_BYTES);
    reading_memory_kernel<<<grid, THREADS, SMEM_BYTES>>>(
        sub_emb, memory, sub_len, sub_raw,
        W_mem, b_mem, W_sub, b_sub, W_gate, b_gate, out, Btot);
}